// round 5
// baseline (speedup 1.0000x reference)
#include <cuda_runtime.h>
#include <cstdint>

#define MDIM  256
#define NHEAD 8
#define HDIM  32
#define SEQ   128
#define BATCH 2
#define P     (BATCH*SEQ*SEQ)   // 32768 positions
#define QKV_N (3*MDIM)          // 768

// ---------------- scratch (device globals; no cudaMalloc allowed) -----------
__device__ float g_qkv[(size_t)P * QKV_N];   // 100.7 MB
__device__ float g_mean[P];
__device__ float g_rstd[P];
__device__ float g_o[(size_t)P * MDIM];      // 33.6 MB
__device__ int   g_mask_is_u8;

// ---------------- mask dtype detector ---------------------------------------
__global__ void detect_mask_kernel(const int* __restrict__ m) {
    __shared__ int flag;
    if (threadIdx.x == 0) flag = 0;
    __syncthreads();
    for (int i = threadIdx.x; i < P / 4; i += 256) {
        int v = m[i];
        if (v != 0 && v != 1) flag = 1;
    }
    __syncthreads();
    if (threadIdx.x == 0) g_mask_is_u8 = flag;
}

// ---------------- LayerNorm statistics: one warp per 256-wide row -----------
__global__ void ln_stats_kernel(const float* __restrict__ x,
                                float* __restrict__ mean,
                                float* __restrict__ rstd) {
    int row = blockIdx.x * blockDim.y + threadIdx.y;
    const float* xr = x + (size_t)row * MDIM;
    float s = 0.f, s2 = 0.f;
    for (int i = threadIdx.x; i < MDIM; i += 32) {
        float v = xr[i];
        s += v; s2 += v * v;
    }
    #pragma unroll
    for (int o = 16; o; o >>= 1) {
        s  += __shfl_xor_sync(0xffffffffu, s, o);
        s2 += __shfl_xor_sync(0xffffffffu, s2, o);
    }
    if (threadIdx.x == 0) {
        float m   = s * (1.f / MDIM);
        float var = fmaxf(s2 * (1.f / MDIM) - m * m, 0.f);
        mean[row] = m;
        rstd[row] = rsqrtf(var + 1e-5f);
    }
}

// ---------------- tf32 helpers ----------------------------------------------
__device__ __forceinline__ float tf32r(float x) {
    uint32_t u;
    asm("cvt.rna.tf32.f32 %0, %1;" : "=r"(u) : "f"(x));
    return __uint_as_float(u);
}

#define MMA_TF32(d, a, b) \
    asm volatile("mma.sync.aligned.m16n8k8.row.col.f32.tf32.tf32.f32 " \
        "{%0,%1,%2,%3}, {%4,%5,%6,%7}, {%8,%9}, {%0,%1,%2,%3};" \
        : "+f"(d[0]), "+f"(d[1]), "+f"(d[2]), "+f"(d[3]) \
        : "r"(a[0]), "r"(a[1]), "r"(a[2]), "r"(a[3]), "r"(b[0]), "r"(b[1]))

// ---------------- 3xTF32 tensor-core GEMM: C[m,n] = sum_k A[m,k]*B[n,k] -----
// BM=128, BN=128, BK=32; 256 threads = 8 warps (2x4), warp tile 64x32.
// Smem layout: [row][BK+4] (stride 36 floats) for A(hi/lo) and B(hi/lo).
#define GBM 128
#define GBN 128
#define GBK 32
#define AST 36                          // BK + 4 pad
#define SM_AH 0
#define SM_AL (128*AST)
#define SM_BH (2*128*AST)
#define SM_BL (3*128*AST)
#define GEMM_SMEM_BYTES (4*128*AST*4)   // 73728 B

template<bool LN>
__global__ __launch_bounds__(256) void gemm_tc_kernel(
    const float* __restrict__ A, const float* __restrict__ Bmat,
    float* __restrict__ C, int M, int N, int K,
    const float* __restrict__ mean, const float* __restrict__ rstd,
    const float* __restrict__ gamma, const float* __restrict__ beta)
{
    extern __shared__ float smd[];
    float* AsH = smd + SM_AH;
    float* AsL = smd + SM_AL;
    float* BsH = smd + SM_BH;
    float* BsL = smd + SM_BL;

    const int tid  = threadIdx.x;
    const int lane = tid & 31;
    const int wid  = tid >> 5;
    const int gid  = lane >> 2;          // 0..7
    const int tig  = lane & 3;           // 0..3
    const int warp_m = (wid & 1) << 6;   // 0,64
    const int warp_n = (wid >> 1) << 5;  // 0,32,64,96
    const int bm = blockIdx.x * GBM;
    const int bn = blockIdx.y * GBN;

    float acc[4][4][4];
    #pragma unroll
    for (int i = 0; i < 4; i++)
        #pragma unroll
        for (int j = 0; j < 4; j++)
            #pragma unroll
            for (int r = 0; r < 4; r++) acc[i][j][r] = 0.f;

    for (int k0 = 0; k0 < K; k0 += GBK) {
        // ---- load + convert A tile (coalesced: 8 lanes cover one 32-k row) --
        #pragma unroll
        for (int seg = 0; seg < 4; seg++) {
            int idx = seg * 256 + tid;
            int m   = idx >> 3;          // 0..127
            int kk  = (idx & 7) << 2;    // 0,4,...,28
            float4 v = *(const float4*)(A + (size_t)(bm + m) * K + k0 + kk);
            if (LN) {
                float mu = mean[bm + m], rs = rstd[bm + m];
                float4 g  = *(const float4*)(gamma + k0 + kk);
                float4 be = *(const float4*)(beta  + k0 + kk);
                v.x = (v.x - mu) * rs * g.x + be.x;
                v.y = (v.y - mu) * rs * g.y + be.y;
                v.z = (v.z - mu) * rs * g.z + be.z;
                v.w = (v.w - mu) * rs * g.w + be.w;
            }
            float hx = tf32r(v.x), hy = tf32r(v.y), hz = tf32r(v.z), hw = tf32r(v.w);
            *(float4*)&AsH[m * AST + kk] = make_float4(hx, hy, hz, hw);
            *(float4*)&AsL[m * AST + kk] = make_float4(
                tf32r(v.x - hx), tf32r(v.y - hy), tf32r(v.z - hz), tf32r(v.w - hw));
        }
        // ---- load + convert B tile ----------------------------------------
        #pragma unroll
        for (int seg = 0; seg < 4; seg++) {
            int idx = seg * 256 + tid;
            int n   = idx >> 3;
            int kk  = (idx & 7) << 2;
            float4 v = *(const float4*)(Bmat + (size_t)(bn + n) * K + k0 + kk);
            float hx = tf32r(v.x), hy = tf32r(v.y), hz = tf32r(v.z), hw = tf32r(v.w);
            *(float4*)&BsH[n * AST + kk] = make_float4(hx, hy, hz, hw);
            *(float4*)&BsL[n * AST + kk] = make_float4(
                tf32r(v.x - hx), tf32r(v.y - hy), tf32r(v.z - hz), tf32r(v.w - hw));
        }
        __syncthreads();

        #pragma unroll
        for (int ks = 0; ks < 4; ks++) {
            const int krow = ks * 8;
            uint32_t aH[4][4], aL[4][4], bH[4][2], bL[4][2];
            #pragma unroll
            for (int mt = 0; mt < 4; mt++) {
                int mb = warp_m + mt * 16 + gid;
                aH[mt][0] = __float_as_uint(AsH[(mb    ) * AST + krow + tig]);
                aH[mt][1] = __float_as_uint(AsH[(mb + 8) * AST + krow + tig]);
                aH[mt][2] = __float_as_uint(AsH[(mb    ) * AST + krow + tig + 4]);
                aH[mt][3] = __float_as_uint(AsH[(mb + 8) * AST + krow + tig + 4]);
                aL[mt][0] = __float_as_uint(AsL[(mb    ) * AST + krow + tig]);
                aL[mt][1] = __float_as_uint(AsL[(mb + 8) * AST + krow + tig]);
                aL[mt][2] = __float_as_uint(AsL[(mb    ) * AST + krow + tig + 4]);
                aL[mt][3] = __float_as_uint(AsL[(mb + 8) * AST + krow + tig + 4]);
            }
            #pragma unroll
            for (int nt = 0; nt < 4; nt++) {
                int nb = warp_n + nt * 8 + gid;
                bH[nt][0] = __float_as_uint(BsH[nb * AST + krow + tig]);
                bH[nt][1] = __float_as_uint(BsH[nb * AST + krow + tig + 4]);
                bL[nt][0] = __float_as_uint(BsL[nb * AST + krow + tig]);
                bL[nt][1] = __float_as_uint(BsL[nb * AST + krow + tig + 4]);
            }
            #pragma unroll
            for (int mt = 0; mt < 4; mt++)
                #pragma unroll
                for (int nt = 0; nt < 4; nt++) {
                    MMA_TF32(acc[mt][nt], aH[mt], bH[nt]);
                    MMA_TF32(acc[mt][nt], aH[mt], bL[nt]);
                    MMA_TF32(acc[mt][nt], aL[mt], bH[nt]);
                }
        }
        __syncthreads();
    }

    // ---- epilogue ----------------------------------------------------------
    #pragma unroll
    for (int mt = 0; mt < 4; mt++) {
        int r0 = bm + warp_m + mt * 16 + gid;
        #pragma unroll
        for (int nt = 0; nt < 4; nt++) {
            int c = bn + warp_n + nt * 8 + 2 * tig;
            *(float2*)&C[(size_t)r0 * N + c] =
                make_float2(acc[mt][nt][0], acc[mt][nt][1]);
            *(float2*)&C[(size_t)(r0 + 8) * N + c] =
                make_float2(acc[mt][nt][2], acc[mt][nt][3]);
        }
    }
}

// ---------------- axial rotary on q,k (first 32 channels only) --------------
__global__ void rotary_kernel(float* __restrict__ qkv) {
    int gid = blockIdx.x * blockDim.x + threadIdx.x;
    if (gid >= P * 16) return;
    int i = gid & 15;
    int p = gid >> 4;
    int y = p & 127;
    int x = (p >> 7) & 127;
    int j = (i < 8) ? i : (i - 8);
    float invf = expf(-(2.f * (float)j / 16.f) * logf(10000.f));
    float t = (i < 8) ? (-1.f + 2.f * (float)x / 127.f)
                      : (-1.f + 2.f * (float)y / 127.f);
    float th = t * invf;
    float c = cosf(th), sn = sinf(th);

    float* q = qkv + (size_t)p * QKV_N + 2 * i;
    float q0 = q[0], q1 = q[1];
    q[0] = q0 * c - q1 * sn;
    q[1] = q1 * c + q0 * sn;
    float* k = q + MDIM;
    float k0 = k[0], k1 = k[1];
    k[0] = k0 * c - k1 * sn;
    k[1] = k1 * c + k0 * sn;
}

// ---------------- attention: single pass (no max needed: |s| <~ 10) ---------
// out = sum_k exp(s_k) v_k / sum_k exp(s_k); masked terms are exactly 0,
// matching the reference where exp(-1e9 - m) underflows to +0 in fp32.
__global__ __launch_bounds__(128) void attn_kernel(
    const float* __restrict__ qkv,
    const unsigned char* __restrict__ mask8,
    const int* __restrict__ mask32,
    float* __restrict__ o)
{
    __shared__ float4 Ks4[SEQ][8];
    __shared__ float4 Vs4[SEQ][8];
    __shared__ unsigned char msk[SEQ];

    int blk = blockIdx.x;
    int h = blk & 7;
    int x = (blk >> 3) & 127;
    int b = blk >> 10;
    int tid = threadIdx.x;
    int rowbase = (b * SEQ + x) * SEQ;

    for (int fi = tid; fi < SEQ * 8; fi += 128) {
        int row = fi >> 3, d4 = fi & 7;
        const float* base = qkv + (size_t)(rowbase + row) * QKV_N + h * HDIM + d4 * 4;
        Ks4[row][d4] = *(const float4*)(base + MDIM);
        Vs4[row][d4] = *(const float4*)(base + 2 * MDIM);
    }
    {
        size_t midx = (size_t)(b * SEQ + x) * SEQ + tid;
        msk[tid] = g_mask_is_u8 ? mask8[midx] : (unsigned char)mask32[midx];
    }

    const float scale = 0.17677669529663687f;  // 32^-0.5 folded into q
    float4 q[8];
    const float4* qp = (const float4*)(qkv + (size_t)(rowbase + tid) * QKV_N + h * HDIM);
    #pragma unroll
    for (int j = 0; j < 8; j++) {
        float4 v = qp[j];
        v.x *= scale; v.y *= scale; v.z *= scale; v.w *= scale;
        q[j] = v;
    }
    __syncthreads();

    float sum = 0.f;
    float4 acc[8];
    #pragma unroll
    for (int j = 0; j < 8; j++) acc[j] = make_float4(0.f, 0.f, 0.f, 0.f);

    #pragma unroll 4
    for (int k = 0; k < SEQ; k++) {
        float s = 0.f;
        #pragma unroll
        for (int j = 0; j < 8; j++) {
            float4 kv = Ks4[k][j];
            s = fmaf(q[j].x, kv.x, s); s = fmaf(q[j].y, kv.y, s);
            s = fmaf(q[j].z, kv.z, s); s = fmaf(q[j].w, kv.w, s);
        }
        float p = msk[k] ? 0.f : __expf(s);
        sum += p;
        #pragma unroll
        for (int j = 0; j < 8; j++) {
            float4 v = Vs4[k][j];
            acc[j].x = fmaf(p, v.x, acc[j].x);
            acc[j].y = fmaf(p, v.y, acc[j].y);
            acc[j].z = fmaf(p, v.z, acc[j].z);
            acc[j].w = fmaf(p, v.w, acc[j].w);
        }
    }
    float inv = 1.f / sum;
    float4* op = (float4*)(o + (size_t)(rowbase + tid) * MDIM + h * HDIM);
    #pragma unroll
    for (int j = 0; j < 8; j++) {
        acc[j].x *= inv; acc[j].y *= inv; acc[j].z *= inv; acc[j].w *= inv;
        op[j] = acc[j];
    }
}

// ---------------- launch ----------------------------------------------------
extern "C" void kernel_launch(void* const* d_in, const int* in_sizes, int n_in,
                              void* d_out, int out_size) {
    const float* pair_act = nullptr;
    const void*  pair_mask = nullptr;
    const float* ln_gamma = nullptr;
    const float* ln_beta  = nullptr;
    const float* Wqkv = nullptr;
    const float* Wout = nullptr;
    for (int i = 0; i < n_in; i++) {
        int sz = in_sizes[i];
        if      (sz == P * MDIM)     pair_act  = (const float*)d_in[i];
        else if (sz == P)            pair_mask = d_in[i];
        else if (sz == QKV_N * MDIM) Wqkv      = (const float*)d_in[i];
        else if (sz == MDIM * MDIM)  Wout      = (const float*)d_in[i];
        else if (sz == MDIM) {
            if (!ln_gamma) ln_gamma = (const float*)d_in[i];
            else           ln_beta  = (const float*)d_in[i];
        }
    }
    float* out = (float*)d_out;

    float *qkv, *meanp, *rstdp, *op;
    cudaGetSymbolAddress((void**)&qkv,   g_qkv);
    cudaGetSymbolAddress((void**)&meanp, g_mean);
    cudaGetSymbolAddress((void**)&rstdp, g_rstd);
    cudaGetSymbolAddress((void**)&op,    g_o);

    cudaFuncSetAttribute(gemm_tc_kernel<true>,
                         cudaFuncAttributeMaxDynamicSharedMemorySize, GEMM_SMEM_BYTES);
    cudaFuncSetAttribute(gemm_tc_kernel<false>,
                         cudaFuncAttributeMaxDynamicSharedMemorySize, GEMM_SMEM_BYTES);

    detect_mask_kernel<<<1, 256>>>((const int*)pair_mask);

    ln_stats_kernel<<<P / 8, dim3(32, 8)>>>(pair_act, meanp, rstdp);

    gemm_tc_kernel<true><<<dim3(P / GBM, QKV_N / GBN), 256, GEMM_SMEM_BYTES>>>(
        pair_act, Wqkv, qkv, P, QKV_N, MDIM, meanp, rstdp, ln_gamma, ln_beta);

    rotary_kernel<<<(P * 16) / 256, 256>>>(qkv);

    attn_kernel<<<BATCH * SEQ * NHEAD, 128>>>(
        qkv, (const unsigned char*)pair_mask, (const int*)pair_mask, op);

    gemm_tc_kernel<false><<<dim3(P / GBM, MDIM / GBN), 256, GEMM_SMEM_BYTES>>>(
        op, Wout, out, P, MDIM, MDIM, nullptr, nullptr, nullptr, nullptr);
}

// round 10
// speedup vs baseline: 1.8713x; 1.8713x over previous
#include <cuda_runtime.h>
#include <cuda_bf16.h>
#include <cstdint>

#define MDIM  256
#define NHEAD 8
#define HDIM  32
#define SEQ   128
#define BATCH 2
#define P     (BATCH*SEQ*SEQ)   // 32768 positions
#define QKV_N (3*MDIM)          // 768

// ---------------- scratch (device globals; no cudaMalloc allowed) -----------
__device__ float g_qkv[(size_t)P * QKV_N];   // 100.7 MB
__device__ float g_mean[P];
__device__ float g_rstd[P];
__device__ float g_o[(size_t)P * MDIM];      // 33.6 MB
__device__ int   g_mask_is_u8;

// ---------------- mask dtype detector ---------------------------------------
__global__ void detect_mask_kernel(const int* __restrict__ m) {
    __shared__ int flag;
    if (threadIdx.x == 0) flag = 0;
    __syncthreads();
    for (int i = threadIdx.x; i < P / 4; i += 256) {
        int v = m[i];
        if (v != 0 && v != 1) flag = 1;
    }
    __syncthreads();
    if (threadIdx.x == 0) g_mask_is_u8 = flag;
}

// ---------------- LayerNorm statistics: one warp per 256-wide row -----------
__global__ void ln_stats_kernel(const float* __restrict__ x,
                                float* __restrict__ mean,
                                float* __restrict__ rstd) {
    int row = blockIdx.x * blockDim.y + threadIdx.y;
    const float* xr = x + (size_t)row * MDIM;
    float s = 0.f, s2 = 0.f;
    for (int i = threadIdx.x; i < MDIM; i += 32) {
        float v = xr[i];
        s += v; s2 += v * v;
    }
    #pragma unroll
    for (int o = 16; o; o >>= 1) {
        s  += __shfl_xor_sync(0xffffffffu, s, o);
        s2 += __shfl_xor_sync(0xffffffffu, s2, o);
    }
    if (threadIdx.x == 0) {
        float m   = s * (1.f / MDIM);
        float var = fmaxf(s2 * (1.f / MDIM) - m * m, 0.f);
        mean[row] = m;
        rstd[row] = rsqrtf(var + 1e-5f);
    }
}

// ---------------- bf16 split-precision tensor-core GEMM ----------------------
// C[m,n] = sum_k A[m,k] * B[n,k], fp32 in/out.
// Each fp32 x is split x = hi + lo (both bf16). D = Ah*Bh + Ah*Bl + Al*Bh.
// BM=128, BN=128, BK=32; 256 threads = 8 warps (2x4), warp tile 64x32.
// Smem word layout per row (36-word stride): word[2*k2+0] = H pair (k=2*k2,2*k2+1),
// word[2*k2+1] = L pair. Fragment fetch = one LDS.64 per (H,L) operand pair.
#define GBM 128
#define GBN 128
#define GBK 32
#define WST 36                           // words per row (32 + 4 pad)

#define MMA_BF16(d, a, b) \
    asm volatile("mma.sync.aligned.m16n8k16.row.col.f32.bf16.bf16.f32 " \
        "{%0,%1,%2,%3}, {%4,%5,%6,%7}, {%8,%9}, {%0,%1,%2,%3};" \
        : "+f"(d[0]), "+f"(d[1]), "+f"(d[2]), "+f"(d[3]) \
        : "r"(a[0]), "r"(a[1]), "r"(a[2]), "r"(a[3]), "r"(b[0]), "r"(b[1]))

__device__ __forceinline__ uint2 split_pack2(float x, float y) {
    // returns {H word, L word}; each word packs two bf16 (low = first elem)
    __nv_bfloat162 h = __float22bfloat162_rn(make_float2(x, y));
    float hx = __bfloat162float(__low2bfloat16(h));
    float hy = __bfloat162float(__high2bfloat16(h));
    __nv_bfloat162 l = __float22bfloat162_rn(make_float2(x - hx, y - hy));
    uint2 r;
    r.x = *(uint32_t*)&h;
    r.y = *(uint32_t*)&l;
    return r;
}

template<bool LN>
__global__ __launch_bounds__(256) void gemm_bf16x3_kernel(
    const float* __restrict__ A, const float* __restrict__ Bmat,
    float* __restrict__ C, int M, int N, int K, int nblk,
    const float* __restrict__ mean, const float* __restrict__ rstd,
    const float* __restrict__ gamma, const float* __restrict__ beta)
{
    __shared__ uint32_t As[128 * WST];
    __shared__ uint32_t Bs[128 * WST];

    const int tid  = threadIdx.x;
    const int lane = tid & 31;
    const int wid  = tid >> 5;
    const int gid  = lane >> 2;          // 0..7
    const int tig  = lane & 3;           // 0..3
    const int warp_m = (wid & 1) << 6;   // 0,64
    const int warp_n = (wid >> 1) << 5;  // 0,32,64,96
    const int bm = (blockIdx.x / nblk) * GBM;   // n-fast ordering (A L2 reuse)
    const int bn = (blockIdx.x % nblk) * GBN;

    float acc[4][4][4];
    #pragma unroll
    for (int i = 0; i < 4; i++)
        #pragma unroll
        for (int j = 0; j < 4; j++)
            #pragma unroll
            for (int r = 0; r < 4; r++) acc[i][j][r] = 0.f;

    const int lm = tid >> 3;             // row handled on loads (0..31 per seg)
    const int lk = (tid & 7) << 2;       // k offset 0,4,...,28

    for (int k0 = 0; k0 < K; k0 += GBK) {
        // ---- load + LN + split A tile -------------------------------------
        #pragma unroll
        for (int seg = 0; seg < 4; seg++) {
            int m = seg * 32 + lm;
            float4 v = *(const float4*)(A + (size_t)(bm + m) * K + k0 + lk);
            if (LN) {
                float mu = mean[bm + m], rs = rstd[bm + m];
                float4 g  = *(const float4*)(gamma + k0 + lk);
                float4 be = *(const float4*)(beta  + k0 + lk);
                v.x = (v.x - mu) * rs * g.x + be.x;
                v.y = (v.y - mu) * rs * g.y + be.y;
                v.z = (v.z - mu) * rs * g.z + be.z;
                v.w = (v.w - mu) * rs * g.w + be.w;
            }
            uint2 p01 = split_pack2(v.x, v.y);
            uint2 p23 = split_pack2(v.z, v.w);
            uint4 w = make_uint4(p01.x, p01.y, p23.x, p23.y);
            *(uint4*)&As[m * WST + lk] = w;
        }
        // ---- load + split B tile ------------------------------------------
        #pragma unroll
        for (int seg = 0; seg < 4; seg++) {
            int n = seg * 32 + lm;
            float4 v = *(const float4*)(Bmat + (size_t)(bn + n) * K + k0 + lk);
            uint2 p01 = split_pack2(v.x, v.y);
            uint2 p23 = split_pack2(v.z, v.w);
            uint4 w = make_uint4(p01.x, p01.y, p23.x, p23.y);
            *(uint4*)&Bs[n * WST + lk] = w;
        }
        __syncthreads();

        #pragma unroll
        for (int ks = 0; ks < 2; ks++) {           // two k16 slices per ktile
            const int k2b = ks * 8;
            uint32_t aH[4][4], aL[4][4], bH[4][2], bL[4][2];
            #pragma unroll
            for (int mt = 0; mt < 4; mt++) {
                int r0 = warp_m + mt * 16 + gid;
                uint2 w0 = *(const uint2*)&As[(r0    ) * WST + 2 * (k2b + tig)];
                uint2 w1 = *(const uint2*)&As[(r0 + 8) * WST + 2 * (k2b + tig)];
                uint2 w2 = *(const uint2*)&As[(r0    ) * WST + 2 * (k2b + 4 + tig)];
                uint2 w3 = *(const uint2*)&As[(r0 + 8) * WST + 2 * (k2b + 4 + tig)];
                aH[mt][0] = w0.x; aL[mt][0] = w0.y;
                aH[mt][1] = w1.x; aL[mt][1] = w1.y;
                aH[mt][2] = w2.x; aL[mt][2] = w2.y;
                aH[mt][3] = w3.x; aL[mt][3] = w3.y;
            }
            #pragma unroll
            for (int nt = 0; nt < 4; nt++) {
                int nb = warp_n + nt * 8 + gid;
                uint2 w0 = *(const uint2*)&Bs[nb * WST + 2 * (k2b + tig)];
                uint2 w1 = *(const uint2*)&Bs[nb * WST + 2 * (k2b + 4 + tig)];
                bH[nt][0] = w0.x; bL[nt][0] = w0.y;
                bH[nt][1] = w1.x; bL[nt][1] = w1.y;
            }
            #pragma unroll
            for (int mt = 0; mt < 4; mt++)
                #pragma unroll
                for (int nt = 0; nt < 4; nt++) {
                    MMA_BF16(acc[mt][nt], aH[mt], bH[nt]);
                    MMA_BF16(acc[mt][nt], aH[mt], bL[nt]);
                    MMA_BF16(acc[mt][nt], aL[mt], bH[nt]);
                }
        }
        __syncthreads();
    }

    // ---- epilogue ----------------------------------------------------------
    #pragma unroll
    for (int mt = 0; mt < 4; mt++) {
        int r0 = bm + warp_m + mt * 16 + gid;
        #pragma unroll
        for (int nt = 0; nt < 4; nt++) {
            int c = bn + warp_n + nt * 8 + 2 * tig;
            *(float2*)&C[(size_t)r0 * N + c] =
                make_float2(acc[mt][nt][0], acc[mt][nt][1]);
            *(float2*)&C[(size_t)(r0 + 8) * N + c] =
                make_float2(acc[mt][nt][2], acc[mt][nt][3]);
        }
    }
}

// ---------------- axial rotary on q,k (first 32 channels only) --------------
__global__ void rotary_kernel(float* __restrict__ qkv) {
    int gid = blockIdx.x * blockDim.x + threadIdx.x;
    if (gid >= P * 16) return;
    int i = gid & 15;
    int p = gid >> 4;
    int y = p & 127;
    int x = (p >> 7) & 127;
    int j = (i < 8) ? i : (i - 8);
    float invf = expf(-(2.f * (float)j / 16.f) * logf(10000.f));
    float t = (i < 8) ? (-1.f + 2.f * (float)x / 127.f)
                      : (-1.f + 2.f * (float)y / 127.f);
    float th = t * invf;
    float c = cosf(th), sn = sinf(th);

    float* q = qkv + (size_t)p * QKV_N + 2 * i;
    float q0 = q[0], q1 = q[1];
    q[0] = q0 * c - q1 * sn;
    q[1] = q1 * c + q0 * sn;
    float* k = q + MDIM;
    float k0 = k[0], k1 = k[1];
    k[0] = k0 * c - k1 * sn;
    k[1] = k1 * c + k0 * sn;
}

// ---------------- attention: single pass (scores bounded, no max needed) ----
__global__ __launch_bounds__(128) void attn_kernel(
    const float* __restrict__ qkv,
    const unsigned char* __restrict__ mask8,
    const int* __restrict__ mask32,
    float* __restrict__ o)
{
    __shared__ float4 Ks4[SEQ][8];
    __shared__ float4 Vs4[SEQ][8];
    __shared__ unsigned char msk[SEQ];

    int blk = blockIdx.x;
    int h = blk & 7;
    int x = (blk >> 3) & 127;
    int b = blk >> 10;
    int tid = threadIdx.x;
    int rowbase = (b * SEQ + x) * SEQ;

    for (int fi = tid; fi < SEQ * 8; fi += 128) {
        int row = fi >> 3, d4 = fi & 7;
        const float* base = qkv + (size_t)(rowbase + row) * QKV_N + h * HDIM + d4 * 4;
        Ks4[row][d4] = *(const float4*)(base + MDIM);
        Vs4[row][d4] = *(const float4*)(base + 2 * MDIM);
    }
    {
        size_t midx = (size_t)(b * SEQ + x) * SEQ + tid;
        msk[tid] = g_mask_is_u8 ? mask8[midx] : (unsigned char)mask32[midx];
    }

    const float scale = 0.17677669529663687f;  // 32^-0.5 folded into q
    float4 q[8];
    const float4* qp = (const float4*)(qkv + (size_t)(rowbase + tid) * QKV_N + h * HDIM);
    #pragma unroll
    for (int j = 0; j < 8; j++) {
        float4 v = qp[j];
        v.x *= scale; v.y *= scale; v.z *= scale; v.w *= scale;
        q[j] = v;
    }
    __syncthreads();

    float sum = 0.f;
    float4 acc[8];
    #pragma unroll
    for (int j = 0; j < 8; j++) acc[j] = make_float4(0.f, 0.f, 0.f, 0.f);

    #pragma unroll 4
    for (int k = 0; k < SEQ; k++) {
        float s = 0.f;
        #pragma unroll
        for (int j = 0; j < 8; j++) {
            float4 kv = Ks4[k][j];
            s = fmaf(q[j].x, kv.x, s); s = fmaf(q[j].y, kv.y, s);
            s = fmaf(q[j].z, kv.z, s); s = fmaf(q[j].w, kv.w, s);
        }
        float p = msk[k] ? 0.f : __expf(s);
        sum += p;
        #pragma unroll
        for (int j = 0; j < 8; j++) {
            float4 v = Vs4[k][j];
            acc[j].x = fmaf(p, v.x, acc[j].x);
            acc[j].y = fmaf(p, v.y, acc[j].y);
            acc[j].z = fmaf(p, v.z, acc[j].z);
            acc[j].w = fmaf(p, v.w, acc[j].w);
        }
    }
    float inv = 1.f / sum;
    float4* op = (float4*)(o + (size_t)(rowbase + tid) * MDIM + h * HDIM);
    #pragma unroll
    for (int j = 0; j < 8; j++) {
        acc[j].x *= inv; acc[j].y *= inv; acc[j].z *= inv; acc[j].w *= inv;
        op[j] = acc[j];
    }
}

// ---------------- launch ----------------------------------------------------
extern "C" void kernel_launch(void* const* d_in, const int* in_sizes, int n_in,
                              void* d_out, int out_size) {
    const float* pair_act = nullptr;
    const void*  pair_mask = nullptr;
    const float* ln_gamma = nullptr;
    const float* ln_beta  = nullptr;
    const float* Wqkv = nullptr;
    const float* Wout = nullptr;
    for (int i = 0; i < n_in; i++) {
        int sz = in_sizes[i];
        if      (sz == P * MDIM)     pair_act  = (const float*)d_in[i];
        else if (sz == P)            pair_mask = d_in[i];
        else if (sz == QKV_N * MDIM) Wqkv      = (const float*)d_in[i];
        else if (sz == MDIM * MDIM)  Wout      = (const float*)d_in[i];
        else if (sz == MDIM) {
            if (!ln_gamma) ln_gamma = (const float*)d_in[i];
            else           ln_beta  = (const float*)d_in[i];
        }
    }
    float* out = (float*)d_out;

    float *qkv, *meanp, *rstdp, *op;
    cudaGetSymbolAddress((void**)&qkv,   g_qkv);
    cudaGetSymbolAddress((void**)&meanp, g_mean);
    cudaGetSymbolAddress((void**)&rstdp, g_rstd);
    cudaGetSymbolAddress((void**)&op,    g_o);

    detect_mask_kernel<<<1, 256>>>((const int*)pair_mask);

    ln_stats_kernel<<<P / 8, dim3(32, 8)>>>(pair_act, meanp, rstdp);

    {
        int nb = QKV_N / GBN;                      // 6
        gemm_bf16x3_kernel<true><<<(P / GBM) * nb, 256>>>(
            pair_act, Wqkv, qkv, P, QKV_N, MDIM, nb,
            meanp, rstdp, ln_gamma, ln_beta);
    }

    rotary_kernel<<<(P * 16) / 256, 256>>>(qkv);

    attn_kernel<<<BATCH * SEQ * NHEAD, 128>>>(
        qkv, (const unsigned char*)pair_mask, (const int*)pair_mask, op);

    {
        int nb = MDIM / GBN;                       // 2
        gemm_bf16x3_kernel<false><<<(P / GBM) * nb, 256>>>(
            op, Wout, out, P, MDIM, MDIM, nb,
            nullptr, nullptr, nullptr, nullptr);
    }
}